// round 2
// baseline (speedup 1.0000x reference)
#include <cuda_runtime.h>
#include <cstdint>

// ---------------------------------------------------------------------------
// C3 layer: x(128,6,256,256) -> out(128,16,252,252), 5x5 VALID convs.
//   oc 0..5  : w3[oc]   over channels CH3[oc]   (3 ch)
//   oc 6..14 : w4[oc-6] over channels CH4[oc-6] (4 ch)
//   oc 15    : w6[0]    over all 6 channels
// Strategy: direct conv, 4 horizontal pixels/thread, all 16 oc per thread.
// Accumulators are packed f32x2 (fma.rn.f32x2 -> FFMA2, 2 FMA/instr).
// Weights staged in smem duplicated as (w,w) pairs -> LDS.64 broadcast is a
// ready FFMA2 operand. Channel wiring is compile-time (POC table) so all
// accumulators stay in registers.
// ---------------------------------------------------------------------------

// For input channel c, the 10 (output-channel, weight-block-offset) pairs.
// Offsets index the concatenated [w3(450) | w4(900) | w6(150)] weight array,
// in units of floats, each block being 25 weights (5x5).
__device__ constexpr int POC[6][10] = {
    {0, 4, 5, 6,  9, 10, 11, 12, 14, 15},
    {0, 1, 5, 6,  7, 10, 11, 12, 13, 15},
    {0, 1, 2, 6,  7,  8, 11, 13, 14, 15},
    {1, 2, 3, 6,  7,  8,  9, 12, 14, 15},
    {2, 3, 4, 7,  8,  9, 10, 12, 13, 15},
    {3, 4, 5, 8,  9, 10, 11, 13, 14, 15}
};
__device__ constexpr int POFF[6][10] = {
    {  0, 300, 375, 450, 750,  850,  950, 1050, 1250, 1350},
    { 25,  75, 400, 475, 550,  875,  975, 1075, 1150, 1375},
    { 50, 100, 150, 500, 575,  650, 1000, 1175, 1275, 1400},
    {125, 175, 225, 525, 600,  675,  775, 1100, 1300, 1425},
    {200, 250, 325, 625, 700,  800,  900, 1125, 1200, 1450},
    {275, 350, 425, 725, 825,  925, 1025, 1225, 1325, 1475}
};

#define FMA2(acc, a, b) asm("fma.rn.f32x2 %0, %1, %2, %0;" : "+l"(acc) : "l"(a), "l"(b))

__device__ __forceinline__ unsigned long long pack2(float lo, float hi) {
    unsigned long long r;
    asm("mov.b64 %0, {%1, %2};" : "=l"(r) : "f"(lo), "f"(hi));
    return r;
}

union F4 {
    float4 f;
    unsigned long long u[2];
};

__global__ __launch_bounds__(256, 2)
void c3_kernel(const float* __restrict__ x,
               const float* __restrict__ w3, const float* __restrict__ b3,
               const float* __restrict__ w4, const float* __restrict__ b4,
               const float* __restrict__ w6, const float* __restrict__ b6,
               float* __restrict__ out)
{
    // Dup-packed weights: [c][j][ky][kx] as (w,w) float2, row padded to 12
    // floats (48B) so each 5-weight row loads as 2x LDS.128 + 1x LDS.64.
    __shared__ __align__(16) float wsm[6 * 10 * 5 * 12];
    __shared__ float bsm[16];

    const int tid = threadIdx.y * 64 + threadIdx.x;

    // Stage weights (1500 source values) into dup-packed smem.
    for (int idx = tid; idx < 1500; idx += 256) {
        int kx = idx % 5;
        int t  = idx / 5;
        int ky = t % 5;  t /= 5;
        int j  = t % 10;
        int c  = t / 10;
        int off = POFF[c][j] + ky * 5 + kx;
        float w = (off < 450) ? w3[off]
                : (off < 1350) ? w4[off - 450]
                               : w6[off - 1350];
        int d = ((c * 10 + j) * 5 + ky) * 12 + kx * 2;
        wsm[d]     = w;
        wsm[d + 1] = w;
    }
    if (tid < 16) {
        bsm[tid] = (tid < 6) ? b3[tid] : (tid < 15) ? b4[tid - 6] : b6[0];
    }
    __syncthreads();

    const int b  = blockIdx.z;
    const int p  = blockIdx.y * 4 + threadIdx.y;   // output row, 0..251
    const int q0 = threadIdx.x * 4;                // output col base, 0..252
    const int ql = (q0 > 248) ? 248 : q0;          // clamp: tx=63 duplicates tx=62

    // 16 output channels x 4 pixels, packed as f32x2 pairs.
    unsigned long long accL[16], accH[16];
    #pragma unroll
    for (int oc = 0; oc < 16; ++oc) {
        accL[oc] = pack2(bsm[oc], bsm[oc]);
        accH[oc] = accL[oc];
    }

    const uint32_t wbase = (uint32_t)__cvta_generic_to_shared(wsm);

    #pragma unroll
    for (int c = 0; c < 6; ++c) {
        const float* xp = x + (((size_t)b * 6 + c) * 256 + p) * 256 + ql;
        for (int ky = 0; ky < 5; ++ky) {
            F4 a0, a1;
            a0.f = *(const float4*)(xp + (size_t)ky * 256);
            a1.f = *(const float4*)(xp + (size_t)ky * 256 + 4);

            // Packed input pairs (v[i], v[i+1]) covering kx shifts 0..4 for
            // pixel pairs (0,1) and (2,3).
            unsigned long long V01 = a0.u[0];
            unsigned long long V23 = a0.u[1];
            unsigned long long V45 = a1.u[0];
            unsigned long long V67 = a1.u[1];
            unsigned long long V12 = pack2(a0.f.y, a0.f.z);
            unsigned long long V34 = pack2(a0.f.w, a1.f.x);
            unsigned long long V56 = pack2(a1.f.y, a1.f.z);

            #pragma unroll
            for (int j = 0; j < 10; ++j) {
                const int oc = POC[c][j];
                const uint32_t wa = wbase + (uint32_t)((((c * 10 + j) * 5 + ky) * 48));
                unsigned long long W0, W1, W2, W3, W4v;
                asm volatile("ld.shared.v2.u64 {%0, %1}, [%2];"
                             : "=l"(W0), "=l"(W1) : "r"(wa));
                asm volatile("ld.shared.v2.u64 {%0, %1}, [%2];"
                             : "=l"(W2), "=l"(W3) : "r"(wa + 16));
                asm volatile("ld.shared.u64 %0, [%1];"
                             : "=l"(W4v) : "r"(wa + 32));

                FMA2(accL[oc], W0, V01);  FMA2(accH[oc], W0, V23);
                FMA2(accL[oc], W1, V12);  FMA2(accH[oc], W1, V34);
                FMA2(accL[oc], W2, V23);  FMA2(accH[oc], W2, V45);
                FMA2(accL[oc], W3, V34);  FMA2(accH[oc], W3, V56);
                FMA2(accL[oc], W4v, V45); FMA2(accH[oc], W4v, V67);
            }
        }
    }

    if (q0 < 252) {
        #pragma unroll
        for (int oc = 0; oc < 16; ++oc) {
            F4 r;
            r.u[0] = accL[oc];
            r.u[1] = accH[oc];
            *(float4*)(out + (((size_t)b * 16 + oc) * 252 + p) * 252 + q0) = r.f;
        }
    }
}

extern "C" void kernel_launch(void* const* d_in, const int* in_sizes, int n_in,
                              void* d_out, int out_size)
{
    const float* x  = (const float*)d_in[0];
    const float* w3 = (const float*)d_in[1];
    const float* b3 = (const float*)d_in[2];
    const float* w4 = (const float*)d_in[3];
    const float* b4 = (const float*)d_in[4];
    const float* w6 = (const float*)d_in[5];
    const float* b6 = (const float*)d_in[6];
    float* out = (float*)d_out;

    dim3 block(64, 4, 1);        // 64*4 px per block row-group
    dim3 grid(1, 63, 128);       // 63*4 = 252 rows, 128 batch
    c3_kernel<<<grid, block>>>(x, w3, b3, w4, b4, w6, b6, out);
}